// round 2
// baseline (speedup 1.0000x reference)
#include <cuda_runtime.h>

#define BB 4
#define LL 1024
#define DD 64
#define UU 32
#define TI 16          // i-rows per CTA
#define JC 64          // k-chunk rows
#define EST 1040       // e-tile row stride (1040 % 32 == 16 -> disjoint bank halves)
#define KST 33         // k-chunk row stride (conflict-free)

// Scratch for projected q (with bh folded, pre-scaled by 2*log2e) and k (pre-scaled).
__device__ float g_q[BB * LL * UU];
__device__ float g_k[BB * LL * UU];

// ---------------------------------------------------------------------------
// Kernel 1: per-row projection. q = (x@Wt + bh) * 2log2e ; k = (x@Wx) * 2log2e
// grid = B*L blocks, 64 threads each.
// ---------------------------------------------------------------------------
__global__ void qk_proj_kernel(const float* __restrict__ x,
                               const float* __restrict__ Wt,
                               const float* __restrict__ Wx,
                               const float* __restrict__ bh) {
    __shared__ float sx[DD];
    const int row = blockIdx.x;
    const int tid = threadIdx.x;
    if (tid < DD) sx[tid] = x[row * DD + tid];
    __syncthreads();

    const int u = tid & 31;
    const float* W = (tid < 32) ? Wt : Wx;
    float acc = 0.0f;
#pragma unroll
    for (int d = 0; d < DD; d++) acc = fmaf(sx[d], W[d * UU + u], acc);

    const float c = 2.0f * 1.4426950408889634f;   // 2*log2(e)
    if (tid < 32) g_q[row * UU + u] = (acc + bh[u]) * c;
    else          g_k[row * UU + u] = acc * c;
}

// ---------------------------------------------------------------------------
// Kernel 2: fused e / softmax / a@X.
// grid = B * (L/TI) blocks, 256 threads.
// smem: e-tile[TI][EST] + k-chunk[JC][KST] + rinv[TI]
// ---------------------------------------------------------------------------
__device__ __forceinline__ float tanh_fast_prescaled(float z) {
    // input z = 2*log2e*(q+k+bh); tanh = 1 - 2/(2^z + 1)
    float t, r;
    asm("ex2.approx.f32 %0, %1;" : "=f"(t) : "f"(z));
    asm("rcp.approx.f32 %0, %1;" : "=f"(r) : "f"(t + 1.0f));
    return fmaf(-2.0f, r, 1.0f);
}

__global__ __launch_bounds__(256, 2)
void attn_kernel(const float* __restrict__ x,
                 const float* __restrict__ Wa,
                 float* __restrict__ out) {
    extern __shared__ float smem[];
    float* et   = smem;                       // TI * EST
    float* kch  = et + TI * EST;              // JC * KST
    float* rinv = kch + JC * KST;             // TI

    const int tid = threadIdx.x;
    const int b   = blockIdx.x / (LL / TI);
    const int i0  = (blockIdx.x % (LL / TI)) * TI;

    // ---------------- Phase A: e[i][j] for the tile ----------------
    const int i_loc = tid >> 4;   // 0..15
    const int jl    = tid & 15;   // 0..15

    float qreg[UU];
    {
        const float* qrow = &g_q[(b * LL + i0 + i_loc) * UU];
#pragma unroll
        for (int u = 0; u < UU; u++) qreg[u] = qrow[u];
    }
    float wa[UU];
#pragma unroll
    for (int u = 0; u < UU; u++) wa[u] = Wa[u];

    const float* kb = &g_k[b * LL * UU];

    for (int jc = 0; jc < LL; jc += JC) {
        __syncthreads();
        // cooperative load of k chunk [JC][UU] -> kch (padded stride)
#pragma unroll
        for (int t = 0; t < (JC * UU) / 256; t++) {
            int idx = tid + t * 256;
            int jr  = idx >> 5;
            int u   = idx & 31;
            kch[jr * KST + u] = kb[(jc + jr) * UU + u];
        }
        __syncthreads();

#pragma unroll
        for (int s = 0; s < JC / 16; s++) {
            const int j = jl + 16 * s;
            const float* krow = &kch[j * KST];
            float e = 0.0f;
#pragma unroll
            for (int u = 0; u < UU; u++) {
                float z = qreg[u] + krow[u];
                e = fmaf(wa[u], tanh_fast_prescaled(z), e);
            }
            et[i_loc * EST + jc + j] = e;   // ba dropped: softmax shift-invariant
        }
    }
    __syncthreads();

    // ---------------- Phase B: softmax per row ----------------
    {
        const int w    = tid >> 5;
        const int lane = tid & 31;
        const float L2E = 1.4426950408889634f;
#pragma unroll
        for (int r = 0; r < 2; r++) {
            const int i = w * 2 + r;
            float* row = &et[i * EST];
            float m = -1e30f;
            for (int j = lane; j < LL; j += 32) m = fmaxf(m, row[j]);
#pragma unroll
            for (int o = 16; o; o >>= 1) m = fmaxf(m, __shfl_xor_sync(0xFFFFFFFFu, m, o));
            float s = 0.0f;
            for (int j = lane; j < LL; j += 32) {
                float p;
                asm("ex2.approx.f32 %0, %1;" : "=f"(p) : "f"((row[j] - m) * L2E));
                row[j] = p;
                s += p;
            }
#pragma unroll
            for (int o = 16; o; o >>= 1) s += __shfl_xor_sync(0xFFFFFFFFu, s, o);
            if (lane == 0) rinv[i] = 1.0f / (s + 1e-8f);
        }
    }
    __syncthreads();

    // ---------------- Phase C: v = a @ X  (float2 vectorized) ----------------
    {
        const int d2 = tid & 31;   // float2 column index (d = 2*d2, 2*d2+1)
        const int ig = tid >> 5;   // 0..7, handles rows ig*2, ig*2+1
        const float2* x2 = (const float2*)(x + (size_t)b * LL * DD);
        const float* p0row = &et[(ig * 2) * EST];
        const float* p1row = &et[(ig * 2 + 1) * EST];

        float2 a0 = make_float2(0.0f, 0.0f);
        float2 a1 = make_float2(0.0f, 0.0f);
#pragma unroll 4
        for (int j = 0; j < LL; j++) {
            float2 xv = x2[j * 32 + d2];
            float p0 = p0row[j];
            float p1 = p1row[j];
            a0.x = fmaf(p0, xv.x, a0.x);
            a0.y = fmaf(p0, xv.y, a0.y);
            a1.x = fmaf(p1, xv.x, a1.x);
            a1.y = fmaf(p1, xv.y, a1.y);
        }
        const float r0 = rinv[ig * 2];
        const float r1 = rinv[ig * 2 + 1];
        float2* o2 = (float2*)(out + (size_t)b * LL * DD);
        const int ia = i0 + ig * 2;
        o2[(size_t)ia * 32 + d2]       = make_float2(a0.x * r0, a0.y * r0);
        o2[(size_t)(ia + 1) * 32 + d2] = make_float2(a1.x * r1, a1.y * r1);
    }
}

// ---------------------------------------------------------------------------
extern "C" void kernel_launch(void* const* d_in, const int* in_sizes, int n_in,
                              void* d_out, int out_size) {
    const float* x   = (const float*)d_in[0];
    const float* Wt  = (const float*)d_in[1];
    const float* Wx  = (const float*)d_in[2];
    const float* Wa  = (const float*)d_in[3];
    const float* bh  = (const float*)d_in[4];
    // d_in[5] = ba   : cancels under softmax (constant shift) -> unused
    // d_in[6] = attention_width : dead code in reference -> unused
    float* out = (float*)d_out;

    const int smem_bytes = (TI * EST + JC * KST + TI) * (int)sizeof(float);
    cudaFuncSetAttribute(attn_kernel, cudaFuncAttributeMaxDynamicSharedMemorySize, smem_bytes);

    qk_proj_kernel<<<BB * LL, 64>>>(x, Wt, Wx, bh);
    attn_kernel<<<BB * (LL / TI), 256, smem_bytes>>>(x, Wa, out);
}

// round 3
// speedup vs baseline: 1.8704x; 1.8704x over previous
#include <cuda_runtime.h>

#define BB 4
#define LL 1024
#define DD 64
#define UU 32
#define TI 16          // i-rows per CTA
#define JC 64          // k-chunk rows
#define EST 1040       // e-tile row stride (1040 % 32 == 16 -> disjoint bank halves)
#define KST 33         // k-chunk row stride (conflict-free)

// Scratch: q = x@Wt + bh (bias folded), k = x@Wx.
__device__ float g_q[BB * LL * UU];
__device__ float g_k[BB * LL * UU];

// ---------------------------------------------------------------------------
// Kernel 1: per-row projection.
// ---------------------------------------------------------------------------
__global__ void qk_proj_kernel(const float* __restrict__ x,
                               const float* __restrict__ Wt,
                               const float* __restrict__ Wx,
                               const float* __restrict__ bh) {
    __shared__ float sx[DD];
    const int row = blockIdx.x;
    const int tid = threadIdx.x;
    if (tid < DD) sx[tid] = x[row * DD + tid];
    __syncthreads();

    const int u = tid & 31;
    const float* W = (tid < 32) ? Wt : Wx;
    float acc = 0.0f;
#pragma unroll
    for (int d = 0; d < DD; d++) acc = fmaf(sx[d], W[d * UU + u], acc);

    if (tid < 32) g_q[row * UU + u] = acc + bh[u];
    else          g_k[row * UU + u] = acc;
}

// ---------------------------------------------------------------------------
__device__ __forceinline__ float tanhf_fast(float z) {
    float t;
    asm("tanh.approx.f32 %0, %1;" : "=f"(t) : "f"(z));
    return t;
}

// ---------------------------------------------------------------------------
// Kernel 2: fused e / softmax / a@X.
// grid = B * (L/TI) blocks, 256 threads.
// ---------------------------------------------------------------------------
__global__ __launch_bounds__(256, 2)
void attn_kernel(const float* __restrict__ x,
                 const float* __restrict__ Wa,
                 float* __restrict__ out) {
    extern __shared__ float smem[];
    float* et   = smem;                       // TI * EST
    float* kch  = et + TI * EST;              // JC * KST
    float* rinv = kch + JC * KST;             // TI

    const int tid = threadIdx.x;
    const int b   = blockIdx.x / (LL / TI);
    const int i0  = (blockIdx.x % (LL / TI)) * TI;

    // ---------------- Phase A: e[i][j] ----------------
    {
        const int i_loc = tid >> 4;   // 0..15
        const int jl    = tid & 15;   // 0..15

        float qreg[UU];
        {
            const float* qrow = &g_q[(b * LL + i0 + i_loc) * UU];
#pragma unroll
            for (int u = 0; u < UU; u++) qreg[u] = qrow[u];
        }
        float wa[UU];
#pragma unroll
        for (int u = 0; u < UU; u++) wa[u] = Wa[u];

        const float* kb = &g_k[b * LL * UU];

        for (int jc = 0; jc < LL; jc += JC) {
            __syncthreads();
#pragma unroll
            for (int t = 0; t < (JC * UU) / 256; t++) {
                int idx = tid + t * 256;
                int jr  = idx >> 5;
                int u   = idx & 31;
                kch[jr * KST + u] = kb[(jc + jr) * UU + u];
            }
            __syncthreads();

#pragma unroll
            for (int s = 0; s < JC / 16; s++) {
                const int j = jl + 16 * s;
                const float* krow = &kch[j * KST];
                float e0 = 0.0f, e1 = 0.0f;
#pragma unroll
                for (int u = 0; u < UU; u += 2) {
                    e0 = fmaf(wa[u],     tanhf_fast(qreg[u]     + krow[u]),     e0);
                    e1 = fmaf(wa[u + 1], tanhf_fast(qreg[u + 1] + krow[u + 1]), e1);
                }
                et[i_loc * EST + jc + j] = e0 + e1;   // ba dropped: shift-invariant
            }
        }
        __syncthreads();
    }

    // ---------------- Phase B: softmax per row ----------------
    {
        const int w    = tid >> 5;
        const int lane = tid & 31;
        const float L2E = 1.4426950408889634f;
#pragma unroll
        for (int r = 0; r < 2; r++) {
            const int i = w * 2 + r;
            float* row = &et[i * EST];
            float m = -1e30f;
            for (int j = lane; j < LL; j += 32) m = fmaxf(m, row[j]);
#pragma unroll
            for (int o = 16; o; o >>= 1) m = fmaxf(m, __shfl_xor_sync(0xFFFFFFFFu, m, o));
            float s = 0.0f;
            for (int j = lane; j < LL; j += 32) {
                float p;
                asm("ex2.approx.f32 %0, %1;" : "=f"(p) : "f"((row[j] - m) * L2E));
                row[j] = p;
                s += p;
            }
#pragma unroll
            for (int o = 16; o; o >>= 1) s += __shfl_xor_sync(0xFFFFFFFFu, s, o);
            if (lane == 0) rinv[i] = 1.0f / (s + 1e-8f);
        }
    }
    __syncthreads();

    // ---------------- Phase C: v = a @ X, j split across warps ----------------
    {
        const int lane = tid & 31;
        const int w    = tid >> 5;          // 0..7, owns j in [w*128, w*128+128)
        const int j0   = w * (LL / 8);
        const float2* x2 = (const float2*)(x + (size_t)b * LL * DD);

        float accx[TI], accy[TI];
#pragma unroll
        for (int i = 0; i < TI; i++) { accx[i] = 0.0f; accy[i] = 0.0f; }

        for (int j = j0; j < j0 + LL / 8; j += 4) {
            float2 xv0 = x2[(j + 0) * 32 + lane];
            float2 xv1 = x2[(j + 1) * 32 + lane];
            float2 xv2 = x2[(j + 2) * 32 + lane];
            float2 xv3 = x2[(j + 3) * 32 + lane];
#pragma unroll
            for (int i = 0; i < TI; i++) {
                float4 p = *(const float4*)&et[i * EST + j];
                accx[i] = fmaf(p.x, xv0.x, accx[i]); accy[i] = fmaf(p.x, xv0.y, accy[i]);
                accx[i] = fmaf(p.y, xv1.x, accx[i]); accy[i] = fmaf(p.y, xv1.y, accy[i]);
                accx[i] = fmaf(p.z, xv2.x, accx[i]); accy[i] = fmaf(p.z, xv2.y, accy[i]);
                accx[i] = fmaf(p.w, xv3.x, accx[i]); accy[i] = fmaf(p.w, xv3.y, accy[i]);
            }
        }
        __syncthreads();   // all warps done reading et -> safe to overwrite

        // partials: part[w*1024 + i*64 + d]  (d = 2*lane, 2*lane+1)
        float* part = et;
#pragma unroll
        for (int i = 0; i < TI; i++) {
            *(float2*)&part[w * 1024 + i * 64 + 2 * lane] = make_float2(accx[i], accy[i]);
        }
        __syncthreads();

        // reduce 8 partials and scale by rinv
        const int ir = tid >> 4;            // 0..15
        const int d4 = (tid & 15) * 4;      // 0..60
        float4 s = make_float4(0.0f, 0.0f, 0.0f, 0.0f);
#pragma unroll
        for (int ww = 0; ww < 8; ww++) {
            float4 pv = *(const float4*)&part[ww * 1024 + ir * 64 + d4];
            s.x += pv.x; s.y += pv.y; s.z += pv.z; s.w += pv.w;
        }
        const float r = rinv[ir];
        float4 o = make_float4(s.x * r, s.y * r, s.z * r, s.w * r);
        *(float4*)&out[((size_t)b * LL + i0 + ir) * DD + d4] = o;
    }
}

// ---------------------------------------------------------------------------
extern "C" void kernel_launch(void* const* d_in, const int* in_sizes, int n_in,
                              void* d_out, int out_size) {
    const float* x   = (const float*)d_in[0];
    const float* Wt  = (const float*)d_in[1];
    const float* Wx  = (const float*)d_in[2];
    const float* Wa  = (const float*)d_in[3];
    const float* bh  = (const float*)d_in[4];
    // d_in[5] = ba : cancels under softmax -> unused
    // d_in[6] = attention_width : dead code in reference -> unused
    float* out = (float*)d_out;

    const int smem_bytes = (TI * EST + JC * KST + TI) * (int)sizeof(float);
    cudaFuncSetAttribute(attn_kernel, cudaFuncAttributeMaxDynamicSharedMemorySize, smem_bytes);

    qk_proj_kernel<<<BB * LL, 64>>>(x, Wt, Wx, bh);
    attn_kernel<<<BB * (LL / TI), 256, smem_bytes>>>(x, Wa, out);
}